// round 5
// baseline (speedup 1.0000x reference)
#include <cuda_runtime.h>

// Fused pre-norm attention-downsampling, warp-per-row design:
//   out[b,s,:] = q[b,s,:] + sum_f (LN(q[b,s]) . LN(k[b,4s+f])) * LN(v[b,4s+f])
// B=4, Sq=2048, Skv=8192, D=1024, factor=4.
// R4: one WARP per output row -> all reductions are warp shuffles, zero block
// barriers on the critical path. w/b and qn staged in smem to bound registers.

#define DD 1024
#define NTHREADS 256
#define CWARPS 8        // warps per CTA, one row each
#define F4 8            // float4 chunks per lane per row (1024/4/32)
#define FACTOR 4
#define LN_EPS 1e-5f

__device__ __forceinline__ float hsum(const float4 a) {
    return (a.x + a.y) + (a.z + a.w);
}
__device__ __forceinline__ float hsq(const float4 a) {
    return (a.x * a.x + a.y * a.y) + (a.z * a.z + a.w * a.w);
}
__device__ __forceinline__ float wred(float x) {
#pragma unroll
    for (int o = 16; o; o >>= 1) x += __shfl_xor_sync(0xffffffffu, x, o);
    return x;
}

__global__ __launch_bounds__(NTHREADS, 2) void attn_ds_kernel(
    const float* __restrict__ q, const float* __restrict__ k,
    const float* __restrict__ v, const float* __restrict__ lnw,
    const float* __restrict__ lnb, float* __restrict__ out) {
    __shared__ float4 sw4[DD / 4];            // ln weight
    __shared__ float4 sb4[DD / 4];            // ln bias
    __shared__ float4 sqn[CWARPS][DD / 4];    // normalized q, one row per warp

    const int tid = threadIdx.x;
    const int wid = tid >> 5;
    const int lane = tid & 31;
    const int row = blockIdx.x * CWARPS + wid;   // 0..8191  (= b*2048 + s)
    const int b = row >> 11;
    const int s = row & 2047;
    const float invD = 1.0f / (float)DD;

    const float4* qp = (const float4*)q + (size_t)row * (DD / 4);
    const size_t kvo = ((size_t)b * 8192 + (size_t)s * FACTOR) * (DD / 4);
    const float4* kp = (const float4*)k + kvo;
    const float4* vp = (const float4*)v + kvo;

    // Front-batched loads: q + k0 + v0 = 24 independent LDG.128 per thread.
    float4 qv[F4], kv[F4], vv[F4];
#pragma unroll
    for (int j = 0; j < F4; j++) qv[j] = qp[lane + 32 * j];
#pragma unroll
    for (int j = 0; j < F4; j++) kv[j] = kp[lane + 32 * j];
#pragma unroll
    for (int j = 0; j < F4; j++) vv[j] = vp[lane + 32 * j];

    // Stage w/b into smem (one barrier in the whole kernel).
    sw4[tid] = ((const float4*)lnw)[tid];
    sb4[tid] = ((const float4*)lnb)[tid];
    __syncthreads();

    // ---- LN(q): warp-local stats ----
    float s1 = 0.f, s2 = 0.f;
#pragma unroll
    for (int j = 0; j < F4; j++) { s1 += hsum(qv[j]); s2 += hsq(qv[j]); }
    s1 = wred(s1);
    s2 = wred(s2);
    const float muq = s1 * invD;
    const float rsq = rsqrtf(fmaf(-muq, muq, s2 * invD) + LN_EPS);

    // qn -> smem; qv registers remain as the residual accumulator.
#pragma unroll
    for (int j = 0; j < F4; j++) {
        const float4 wv = sw4[lane + 32 * j];
        const float4 bv = sb4[lane + 32 * j];
        float4 qn;
        qn.x = fmaf((qv[j].x - muq) * rsq, wv.x, bv.x);
        qn.y = fmaf((qv[j].y - muq) * rsq, wv.y, bv.y);
        qn.z = fmaf((qv[j].z - muq) * rsq, wv.z, bv.z);
        qn.w = fmaf((qv[j].w - muq) * rsq, wv.w, bv.w);
        sqn[wid][lane + 32 * j] = qn;
    }
    __syncwarp();

#pragma unroll
    for (int f = 0; f < FACTOR; f++) {
        // ---- k & v stats (4 warp reductions) ----
        float ks = 0.f, kss = 0.f, vs = 0.f, vss = 0.f;
#pragma unroll
        for (int j = 0; j < F4; j++) {
            ks += hsum(kv[j]); kss += hsq(kv[j]);
            vs += hsum(vv[j]); vss += hsq(vv[j]);
        }
        ks = wred(ks); kss = wred(kss); vs = wred(vs); vss = wred(vss);
        const float muk = ks * invD;
        const float rsk = rsqrtf(fmaf(-muk, muk, kss * invD) + LN_EPS);
        const float muv = vs * invD;
        const float rsv = rsqrtf(fmaf(-muv, muv, vss * invD) + LN_EPS);

        // ---- pass 1: dot(qn, kn); bake vn into the dying k registers ----
        float4 dot4 = make_float4(0.f, 0.f, 0.f, 0.f);
#pragma unroll
        for (int j = 0; j < F4; j++) {
            const float4 wv = sw4[lane + 32 * j];
            const float4 bv = sb4[lane + 32 * j];
            const float4 qn = sqn[wid][lane + 32 * j];
            const float4 kk = kv[j];
            const float4 vk = vv[j];
            dot4.x = fmaf(qn.x, fmaf((kk.x - muk) * rsk, wv.x, bv.x), dot4.x);
            dot4.y = fmaf(qn.y, fmaf((kk.y - muk) * rsk, wv.y, bv.y), dot4.y);
            dot4.z = fmaf(qn.z, fmaf((kk.z - muk) * rsk, wv.z, bv.z), dot4.z);
            dot4.w = fmaf(qn.w, fmaf((kk.w - muk) * rsk, wv.w, bv.w), dot4.w);
            kv[j].x = fmaf((vk.x - muv) * rsv, wv.x, bv.x);
            kv[j].y = fmaf((vk.y - muv) * rsv, wv.y, bv.y);
            kv[j].z = fmaf((vk.z - muv) * rsv, wv.z, bv.z);
            kv[j].w = fmaf((vk.w - muv) * rsv, wv.w, bv.w);
        }

        // prefetch next v into freed vv registers, overlapping the dot reduce
        if (f < FACTOR - 1) {
#pragma unroll
            for (int j = 0; j < F4; j++)
                vv[j] = vp[(f + 1) * (DD / 4) + lane + 32 * j];
        }

        const float wt = wred(hsum(dot4));

        // ---- pass 2: accumulate residual += wt * vn ----
#pragma unroll
        for (int j = 0; j < F4; j++) {
            qv[j].x = fmaf(wt, kv[j].x, qv[j].x);
            qv[j].y = fmaf(wt, kv[j].y, qv[j].y);
            qv[j].z = fmaf(wt, kv[j].z, qv[j].z);
            qv[j].w = fmaf(wt, kv[j].w, qv[j].w);
        }

        // prefetch next k into freed kv registers
        if (f < FACTOR - 1) {
#pragma unroll
            for (int j = 0; j < F4; j++)
                kv[j] = kp[(f + 1) * (DD / 4) + lane + 32 * j];
        }
    }

    float4* op = (float4*)out + (size_t)row * (DD / 4);
#pragma unroll
    for (int j = 0; j < F4; j++) op[lane + 32 * j] = qv[j];
}

extern "C" void kernel_launch(void* const* d_in, const int* in_sizes, int n_in,
                              void* d_out, int out_size) {
    const float* q   = (const float*)d_in[0];  // query     [4,2048,1024]
    const float* k   = (const float*)d_in[1];  // key       [4,8192,1024]
    const float* v   = (const float*)d_in[2];  // value     [4,8192,1024]
    const float* lnw = (const float*)d_in[3];  // ln_weight [1024]
    const float* lnb = (const float*)d_in[4];  // ln_bias   [1024]
    float* out = (float*)d_out;                // [4,2048,1024]

    attn_ds_kernel<<<8192 / CWARPS, NTHREADS>>>(q, k, v, lnw, lnb, out);
}